// round 15
// baseline (speedup 1.0000x reference)
#include <cuda_runtime.h>
#include <cuda_bf16.h>
#include <math.h>

// Problem constants
#define BB 8
#define NN 2048
#define MM 2048
#define HH 512
#define KD 64

// ---------------- scratch (no allocations allowed) ----------------
__device__ float g_qn[BB * NN];
__device__ float g_kn[BB * MM];
__device__ float g_w[BB * NN];
__device__ __nv_bfloat16 g_qh[BB * NN * KD];      // q hi
__device__ __nv_bfloat16 g_ql[BB * NN * KD];      // q lo
__device__ __nv_bfloat16 g_kh[BB * MM * KD];      // (-2k) hi
__device__ __nv_bfloat16 g_kl[BB * MM * KD];      // (-2k) lo
__device__ __nv_bfloat16 g_wh[2][KD * HH];
__device__ __nv_bfloat16 g_wl[2][KD * HH];

__device__ __forceinline__ unsigned smem_u32(const void* p) {
    unsigned a;
    asm("{ .reg .u64 t; cvta.to.shared.u64 t, %1; cvt.u32.u64 %0, t; }" : "=r"(a) : "l"(p));
    return a;
}

#define CP16(dst, src) asm volatile("cp.async.cg.shared.global [%0], [%1], 16;" :: "r"(dst), "l"(src) : "memory")
#define CP_COMMIT()    asm volatile("cp.async.commit_group;" ::: "memory")
#define CP_WAIT1()     asm volatile("cp.async.wait_group 1;" ::: "memory")
#define CP_WAIT0()     asm volatile("cp.async.wait_group 0;" ::: "memory")

#define LDSM4(r0, r1, r2, r3, a) \
    asm volatile("ldmatrix.sync.aligned.m8n8.x4.shared.b16 {%0,%1,%2,%3}, [%4];" \
                 : "=r"(r0), "=r"(r1), "=r"(r2), "=r"(r3) : "r"(a))

#define MMA16816(c, a, b) \
    asm volatile("mma.sync.aligned.m16n8k16.row.col.f32.bf16.bf16.f32 " \
                 "{%0,%1,%2,%3}, {%4,%5,%6,%7}, {%8,%9}, {%0,%1,%2,%3};" \
                 : "+f"((c)[0]), "+f"((c)[1]), "+f"((c)[2]), "+f"((c)[3]) \
                 : "r"((a)[0]), "r"((a)[1]), "r"((a)[2]), "r"((a)[3]), \
                   "r"((b)[0]), "r"((b)[1]))

// Truncation-based hi/lo split of 2 floats.
__device__ __forceinline__ void split2(float a, float b, unsigned& hp, unsigned& lp) {
    unsigned ua = __float_as_uint(a);
    unsigned ub = __float_as_uint(b);
    hp = __byte_perm(ua, ub, 0x7632);
    float la = a - __uint_as_float(ua & 0xFFFF0000u);
    float lb = b - __uint_as_float(ub & 0xFFFF0000u);
    asm("cvt.rn.bf16x2.f32 %0, %1, %2;" : "=r"(lp) : "f"(lb), "f"(la));
}

// =====================================================================
// Kernel 0: split W into hi/lo bf16
// =====================================================================
__global__ void wsplit_kernel(const float* __restrict__ Wq, const float* __restrict__ Wk)
{
    int i = blockIdx.x * 256 + threadIdx.x;
    int side = i >> 15, j = i & 32767;
    float v = (side ? Wk : Wq)[j];
    __nv_bfloat16 h = __float2bfloat16_rn(v);
    g_wh[side][j] = h;
    g_wl[side][j] = __float2bfloat16_rn(v - __bfloat162float(h));
}

// =====================================================================
// Kernel 1 (v5): HMMA split-bf16 projection, 32-row tiles to kill the
// wave-quantization tail (1024 CTAs over 444 slots = 3 short rounds
// instead of 2 long ones).
// grid = (512, 2), block = 256 (8 warps: 2 rowgroups x 4 colgroups),
// 3 CTAs/SM. smem: xh[4K] xl[4K] | W double buf 2x16K = 40K.
// =====================================================================
#define PJ_XL   4096
#define PJ_W    8192
#define PJ_SMEM 40960

__global__ __launch_bounds__(256, 3) void proj_kernel(
    const float* __restrict__ X0, const float* __restrict__ Y0,
    const float* __restrict__ bq, const float* __restrict__ bk)
{
    extern __shared__ char smem[];
    const unsigned sb = smem_u32(smem);

    const int side = blockIdx.y;
    const float* X    = side ? Y0 : X0;
    const float* bias = side ? bk : bq;
    const char* gwh = (const char*)g_wh[side];
    const char* gwl = (const char*)g_wl[side];
    float* gnorm = side ? g_kn : g_qn;
    __nv_bfloat16* gh = side ? g_kh : g_qh;
    __nv_bfloat16* gl = side ? g_kl : g_ql;
    const float scale = side ? -2.f : 1.f;

    const int r0 = blockIdx.x * 32;
    const int t  = threadIdx.x;
    const int wid = t >> 5, l = t & 31;
    const int wr = (wid & 1) * 16;      // 2 rowgroups x 16 rows
    const int wc = (wid >> 1) * 16;     // 4 colgroups x 16 cols

    // x LDG geometry: 256 16B chunks = [32 rows][8 ch]; 1 chunk per thread
    const int xrow = t >> 3, xch = t & 7;
    const float* xsrc = X + (size_t)(r0 + xrow) * HH + xch * 8;
    const unsigned xoff = xrow * 128 + ((xch * 16) ^ ((xrow & 7) << 4));

    float4 xbuf[2];
    xbuf[0] = *(const float4*)xsrc;
    xbuf[1] = *(const float4*)(xsrc + 4);

#pragma unroll
    for (int it = 0; it < 4; ++it) {
        int f = t + 256 * it;              // 0..1023
        int split = f >> 9, c = f & 511;
        int row = c >> 3, ch = c & 7;
        unsigned dst = sb + PJ_W + split * 8192 + row * 128 + ((ch * 16) ^ ((row & 7) << 4));
        CP16(dst, (split ? gwl : gwh) + row * 1024 + ch * 16);
    }
    CP_COMMIT();

    // ldmatrix geometry
    const int rowA0 = wr + (l & 7) + ((l & 8) ? 8 : 0);
    const int rowB0 = wc + (l & 7) + ((l & 16) ? 8 : 0);
    const int kbA = (l & 16) ? 16 : 0;
    const int kbB = (l & 8) ? 16 : 0;
    const int p = (l & 7) << 4;
    const unsigned aA0 = sb + rowA0 * 128;
    const unsigned aB0 = rowB0 * 128;

    float acc[2][4];
#pragma unroll
    for (int t8 = 0; t8 < 2; ++t8)
#pragma unroll
        for (int e = 0; e < 4; ++e) acc[t8][e] = 0.f;

    for (int i = 0; i < 8; ++i) {
        __syncthreads();
        // convert + store x chunk i
        {
            float4 a = xbuf[0], b4 = xbuf[1];
            unsigned h0, h1, h2, h3, l0, l1, l2, l3;
            split2(a.x,  a.y,  h0, l0);
            split2(a.z,  a.w,  h1, l1);
            split2(b4.x, b4.y, h2, l2);
            split2(b4.z, b4.w, h3, l3);
            *(uint4*)(smem + xoff)         = make_uint4(h0, h1, h2, h3);
            *(uint4*)(smem + PJ_XL + xoff) = make_uint4(l0, l1, l2, l3);
        }
        if (i < 7) {
            xbuf[0] = *(const float4*)(xsrc + (i + 1) * 64);
            xbuf[1] = *(const float4*)(xsrc + (i + 1) * 64 + 4);
#pragma unroll
            for (int it = 0; it < 4; ++it) {
                int f = t + 256 * it;
                int split = f >> 9, c = f & 511;
                int row = c >> 3, ch = c & 7;
                unsigned dst = sb + PJ_W + ((i + 1) & 1) * 16384 + split * 8192
                               + row * 128 + ((ch * 16) ^ ((row & 7) << 4));
                CP16(dst, (split ? gwl : gwh) + row * 1024 + (i + 1) * 128 + ch * 16);
            }
            CP_COMMIT();
            CP_WAIT1();
        } else {
            CP_WAIT0();
        }
        __syncthreads();

        const unsigned wb = sb + PJ_W + (i & 1) * 16384;
#pragma unroll
        for (int ks = 0; ks < 4; ++ks) {
            const unsigned xbA = (unsigned)((ks * 32 + kbA) ^ p);
            const unsigned xbB = (unsigned)((ks * 32 + kbB) ^ p);
            unsigned ah[4], al[4], bh[2][2], bl[2][2];
            LDSM4(ah[0], ah[1], ah[2], ah[3], aA0 + xbA);
            LDSM4(al[0], al[1], al[2], al[3], aA0 + PJ_XL + xbA);
            {
                unsigned base = wb + aB0 + xbB;
                LDSM4(bh[0][0], bh[0][1], bh[1][0], bh[1][1], base);
                LDSM4(bl[0][0], bl[0][1], bl[1][0], bl[1][1], base + 8192);
            }
#pragma unroll
            for (int t8 = 0; t8 < 2; ++t8) {
                MMA16816(acc[t8], ah, bh[t8]);
                MMA16816(acc[t8], ah, bl[t8]);
                MMA16816(acc[t8], al, bh[t8]);
            }
        }
    }

    // ---- epilogue: bias, stage to s_o[32][68], split writeout, norms ----
    __syncthreads();
    float* s_o = (float*)smem;
#pragma unroll
    for (int t8 = 0; t8 < 2; ++t8) {
        int col = wc + t8 * 8 + 2 * (l & 3);
        float2 b2 = *(const float2*)&bias[col];
        int row0 = wr + (l >> 2);
        s_o[row0 * 68 + col]           = acc[t8][0] + b2.x;
        s_o[row0 * 68 + col + 1]       = acc[t8][1] + b2.y;
        s_o[(row0 + 8) * 68 + col]     = acc[t8][2] + b2.x;
        s_o[(row0 + 8) * 68 + col + 1] = acc[t8][3] + b2.y;
    }
    __syncthreads();

#pragma unroll
    for (int it = 0; it < 2; ++it) {
        int f = t + 256 * it;               // 0..511 over [32 rows][16 quads]
        int quad = f & 15, r = f >> 4;
        float4 v = *(const float4*)&s_o[r * 68 + quad * 4];
        v.x *= scale; v.y *= scale; v.z *= scale; v.w *= scale;
        unsigned hp0, hp1, lp0, lp1;
        split2(v.x, v.y, hp0, lp0);
        split2(v.z, v.w, hp1, lp1);
        size_t base = (size_t)(r0 + r) * KD + quad * 4;
        *(unsigned*)&gh[base]     = hp0;
        *(unsigned*)&gh[base + 2] = hp1;
        *(unsigned*)&gl[base]     = lp0;
        *(unsigned*)&gl[base + 2] = lp1;
    }
    if (t < 32) {
        float s = 0.f;
#pragma unroll
        for (int j = 0; j < 64; ++j) {
            float v = s_o[t * 68 + j];
            s += v * v;
        }
        gnorm[r0 + t] = s;
    }
}

// =====================================================================
// Kernel 2 (v8): hi-only HMMA argmin sweep + FUSED exact refinement.
// grid = (16, 8), block = 256 (8 warps: 4 row x 2 col groups), 2 CTAs/SM.
// =====================================================================
#define D_B     16384
#define BUFSZ   16896
#define D_RV    (D_B + 2 * BUFSZ)       /* 50176 */
#define D_RI    (D_RV + 4096)           /* 54272 */
#define D_CD    (D_RI + 4096)           /* 58368: int2 cand[128] */
#define DIST_SMEM (D_CD + 1024)         /* 59392 */
#define NT 16

__global__ __launch_bounds__(256, 2) void dist_kernel()
{
    extern __shared__ char smem[];
    const unsigned sb = smem_u32(smem);

    const int b  = blockIdx.y;
    const int n0 = blockIdx.x * 128;
    const int t  = threadIdx.x;
    const int wid = t >> 5, l = t & 31;
    const int wr = (wid & 3) * 32;
    const int wc = (wid >> 2) * 64;

    const char* gqh = (const char*)g_qh + ((size_t)b * NN + n0) * KD * 2;
    const char* gkh = (const char*)g_kh + (size_t)b * MM * KD * 2;
    const char* gkn = (const char*)g_kn + (size_t)b * MM * 4;

#pragma unroll
    for (int it = 0; it < 4; ++it) {
        int c = t + 256 * it;
        int row = c >> 3, ch = c & 7;
        unsigned dst = sb + row * 128 + ((ch * 16) ^ ((row & 7) << 4));
        CP16(dst, gqh + c * 16);
    }
#pragma unroll
    for (int it = 0; it < 4; ++it) {
        int c = t + 256 * it;
        int row = c >> 3, ch = c & 7;
        unsigned dst = sb + D_B + row * 128 + ((ch * 16) ^ ((row & 7) << 4));
        CP16(dst, gkh + c * 16);
    }
    if (t < 32) CP16(sb + D_B + 16384 + t * 16, gkn + t * 16);
    CP_COMMIT();

    {
        const char* skh = gkh + (size_t)128 * KD * 2;
        unsigned bufb = sb + D_B + BUFSZ;
#pragma unroll
        for (int it = 0; it < 4; ++it) {
            int c = t + 256 * it;
            int row = c >> 3, ch = c & 7;
            unsigned dst = bufb + row * 128 + ((ch * 16) ^ ((row & 7) << 4));
            CP16(dst, skh + c * 16);
        }
        if (t < 32) CP16(bufb + 16384 + t * 16, gkn + 512 + t * 16);
        CP_COMMIT();
    }

    const int rowA0 = wr + (l & 7) + ((l & 8) ? 8 : 0);
    const int rowB0 = wc + (l & 7) + ((l & 16) ? 8 : 0);
    const int kbA = (l & 16) ? 16 : 0;
    const int kbB = (l & 8) ? 16 : 0;
    const int p = (l & 7) << 4;
    const unsigned aA0 = sb + rowA0 * 128;
    const unsigned aB0 = rowB0 * 128;

    CP_WAIT1();
    __syncthreads();

    float minv[4];
    int   mini[4];
#pragma unroll
    for (int s = 0; s < 4; ++s) { minv[s] = 1e30f; mini[s] = 0; }

    for (int i = 0; i < NT; ++i) {
        const unsigned bufb = sb + D_B + (i & 1) * BUFSZ;

        float acc[2][8][4];
#pragma unroll
        for (int t8 = 0; t8 < 8; ++t8) {
            float2 kn2 = *(const float2*)(smem + D_B + (i & 1) * BUFSZ + 16384
                                          + (wc + t8 * 8 + 2 * (l & 3)) * 4);
#pragma unroll
            for (int f = 0; f < 2; ++f) {
                acc[f][t8][0] = kn2.x; acc[f][t8][1] = kn2.y;
                acc[f][t8][2] = kn2.x; acc[f][t8][3] = kn2.y;
            }
        }

#pragma unroll
        for (int ks = 0; ks < 4; ++ks) {
            const unsigned xbA = (unsigned)((ks * 32 + kbA) ^ p);
            const unsigned xbB = (unsigned)((ks * 32 + kbB) ^ p);
            unsigned ah[2][4], bh[8][2];
#pragma unroll
            for (int f = 0; f < 2; ++f)
                LDSM4(ah[f][0], ah[f][1], ah[f][2], ah[f][3], aA0 + f * 2048 + xbA);
#pragma unroll
            for (int g = 0; g < 4; ++g) {
                unsigned base = bufb + aB0 + g * 2048 + xbB;
                LDSM4(bh[2 * g][0], bh[2 * g][1], bh[2 * g + 1][0], bh[2 * g + 1][1], base);
            }
#pragma unroll
            for (int f = 0; f < 2; ++f)
#pragma unroll
                for (int t8 = 0; t8 < 8; ++t8)
                    MMA16816(acc[f][t8], ah[f], bh[t8]);
        }

        const int mbase = i * 128 + wc + 2 * (l & 3);
#pragma unroll
        for (int f = 0; f < 2; ++f)
#pragma unroll
            for (int t8 = 0; t8 < 8; ++t8) {
                int m0 = mbase + t8 * 8;
                float v0 = acc[f][t8][0], v1 = acc[f][t8][1];
                float v2 = acc[f][t8][2], v3 = acc[f][t8][3];
                int s0 = f * 2, s1 = f * 2 + 1;
                float m01 = fminf(v0, v1);
                int   i01 = (v1 < v0) ? m0 + 1 : m0;
                mini[s0] = (m01 < minv[s0]) ? i01 : mini[s0];
                minv[s0] = fminf(m01, minv[s0]);
                float m23 = fminf(v2, v3);
                int   i23 = (v3 < v2) ? m0 + 1 : m0;
                mini[s1] = (m23 < minv[s1]) ? i23 : mini[s1];
                minv[s1] = fminf(m23, minv[s1]);
            }

        __syncthreads();
        if (i + 2 < NT) {
            const char* skh = gkh + (size_t)(i + 2) * 128 * KD * 2;
            unsigned nbuf = sb + D_B + (i & 1) * BUFSZ;
#pragma unroll
            for (int it = 0; it < 4; ++it) {
                int c = t + 256 * it;
                int row = c >> 3, ch = c & 7;
                unsigned dst = nbuf + row * 128 + ((ch * 16) ^ ((row & 7) << 4));
                CP16(dst, skh + c * 16);
            }
            if (t < 32) CP16(nbuf + 16384 + t * 16, gkn + (size_t)(i + 2) * 512 + t * 16);
            CP_COMMIT();
            CP_WAIT1();
            __syncthreads();
        } else if (i + 1 < NT) {
            CP_WAIT0();
            __syncthreads();
        }
    }

    float* s_rv = (float*)(smem + D_RV);
    int*   s_ri = (int*)(smem + D_RI);
    int2*  s_cd = (int2*)(smem + D_CD);
#pragma unroll
    for (int f = 0; f < 2; ++f)
#pragma unroll
        for (int h = 0; h < 2; ++h) {
            int row = wr + f * 16 + (l >> 2) + h * 8;
            int col8 = (wid >> 2) * 4 + (l & 3);
            s_rv[row * 8 + col8] = minv[f * 2 + h];
            s_ri[row * 8 + col8] = mini[f * 2 + h];
        }
    __syncthreads();
    if (t < 128) {
        float bv1 = 1e30f, bv2 = 1e30f;
        int bi1 = 0, bi2 = 0;
#pragma unroll
        for (int j = 0; j < 8; ++j) {
            float v = s_rv[t * 8 + j];
            int   m = s_ri[t * 8 + j];
            bool better1 = v < bv1;
            float ov = bv1; int oi = bi1;
            bv1 = better1 ? v : bv1;  bi1 = better1 ? m : bi1;
            float cv = better1 ? ov : v;
            int   ci = better1 ? oi : m;
            bool better2 = cv < bv2;
            bv2 = better2 ? cv : bv2; bi2 = better2 ? ci : bi2;
        }
        s_cd[t] = make_int2(bi1, bi2);
    }
    __syncthreads();

    // ---- fused exact refinement: warp handles 16 rows; half-warp per cand.
    {
        const unsigned* uqh = (const unsigned*)g_qh;
        const unsigned* uql = (const unsigned*)g_ql;
        const unsigned* ukh = (const unsigned*)g_kh;
        const unsigned* ukl = (const unsigned*)g_kl;
        const int ll = l & 15;
        for (int rr = 0; rr < 16; ++rr) {
            int row = wid * 16 + rr;
            int grow = b * NN + n0 + row;
            int2 cd = s_cd[row];
            int c = (l < 16) ? cd.x : cd.y;
            size_t qb = (size_t)grow * 32 + ll * 2;
            size_t kb = ((size_t)b * MM + c) * 32 + ll * 2;
            float dot = 0.f;
#pragma unroll
            for (int u = 0; u < 2; ++u) {
                float2 qh = __bfloat1622float2(*(const __nv_bfloat162*)&uqh[qb + u]);
                float2 ql = __bfloat1622float2(*(const __nv_bfloat162*)&uql[qb + u]);
                float2 kh = __bfloat1622float2(*(const __nv_bfloat162*)&ukh[kb + u]);
                float2 kl = __bfloat1622float2(*(const __nv_bfloat162*)&ukl[kb + u]);
                float q0 = qh.x + ql.x, q1 = qh.y + ql.y;
                float k0 = kh.x + kl.x, k1 = kh.y + kl.y;
                dot = fmaf(q0, k0, dot);
                dot = fmaf(q1, k1, dot);
            }
#pragma unroll
            for (int off = 8; off > 0; off >>= 1)
                dot += __shfl_xor_sync(0xFFFFFFFFu, dot, off);
            if (ll == 0) dot += g_kn[b * MM + c];
            float other = __shfl_xor_sync(0xFFFFFFFFu, dot, 16);
            if (l == 0) {
                float dmin = fminf(dot, other) + g_qn[grow];
                g_w[grow] = expf(-dmin);
            }
        }
    }
}

// =====================================================================
// Kernel 3: rank-1 outer product, 4 rows per CTA, streaming stores.
// =====================================================================
__global__ __launch_bounds__(256) void outer_kernel(float* __restrict__ out)
{
    const int b = blockIdx.y;
    const int n0 = blockIdx.x * 4;
    const float* wrow = &g_w[b * NN];
    const float w0 = wrow[n0], w1 = wrow[n0 + 1], w2 = wrow[n0 + 2], w3 = wrow[n0 + 3];
    const float4* wv = (const float4*)wrow;
    float4* o = (float4*)(out + ((size_t)b * NN + n0) * MM);
#pragma unroll
    for (int it = 0; it < 2; ++it) {
        int j = threadIdx.x + 256 * it;
        float4 v = wv[j];
        __stcs(&o[j],        make_float4(w0 * v.x, w0 * v.y, w0 * v.z, w0 * v.w));
        __stcs(&o[j + 512],  make_float4(w1 * v.x, w1 * v.y, w1 * v.z, w1 * v.w));
        __stcs(&o[j + 1024], make_float4(w2 * v.x, w2 * v.y, w2 * v.z, w2 * v.w));
        __stcs(&o[j + 1536], make_float4(w3 * v.x, w3 * v.y, w3 * v.z, w3 * v.w));
    }
}

// =====================================================================
extern "C" void kernel_launch(void* const* d_in, const int* in_sizes, int n_in,
                              void* d_out, int out_size)
{
    const float* x  = (const float*)d_in[0];
    const float* y  = (const float*)d_in[1];
    const float* Wq = (const float*)d_in[2];
    const float* bq = (const float*)d_in[3];
    const float* Wk = (const float*)d_in[4];
    const float* bk = (const float*)d_in[5];
    float* out = (float*)d_out;

    cudaFuncSetAttribute(proj_kernel, cudaFuncAttributeMaxDynamicSharedMemorySize, PJ_SMEM);
    cudaFuncSetAttribute(dist_kernel, cudaFuncAttributeMaxDynamicSharedMemorySize, DIST_SMEM);

    wsplit_kernel<<<256, 256>>>(Wq, Wk);
    proj_kernel<<<dim3(NN * BB / 32, 2), 256, PJ_SMEM>>>(x, y, bq, bk);
    dist_kernel<<<dim3(NN / 128, BB), 256, DIST_SMEM>>>();
    outer_kernel<<<dim3(NN / 4, BB), 256>>>(out);
}

// round 16
// speedup vs baseline: 1.0622x; 1.0622x over previous
#include <cuda_runtime.h>
#include <cuda_bf16.h>
#include <math.h>

// Problem constants
#define BB 8
#define NN 2048
#define MM 2048
#define HH 512
#define KD 64

// ---------------- scratch (no allocations allowed) ----------------
__device__ float g_qn[BB * NN];
__device__ float g_kn[BB * MM];
__device__ float g_w[BB * NN];
__device__ __nv_bfloat16 g_qh[BB * NN * KD];      // q hi
__device__ __nv_bfloat16 g_ql[BB * NN * KD];      // q lo
__device__ __nv_bfloat16 g_kh[BB * MM * KD];      // (-2k) hi
__device__ __nv_bfloat16 g_kl[BB * MM * KD];      // (-2k) lo
__device__ __nv_bfloat16 g_wh[2][KD * HH];
__device__ __nv_bfloat16 g_wl[2][KD * HH];

__device__ __forceinline__ unsigned smem_u32(const void* p) {
    unsigned a;
    asm("{ .reg .u64 t; cvta.to.shared.u64 t, %1; cvt.u32.u64 %0, t; }" : "=r"(a) : "l"(p));
    return a;
}

#define CP16(dst, src) asm volatile("cp.async.cg.shared.global [%0], [%1], 16;" :: "r"(dst), "l"(src) : "memory")
#define CP_COMMIT()    asm volatile("cp.async.commit_group;" ::: "memory")
#define CP_WAIT1()     asm volatile("cp.async.wait_group 1;" ::: "memory")
#define CP_WAIT0()     asm volatile("cp.async.wait_group 0;" ::: "memory")

#define LDSM4(r0, r1, r2, r3, a) \
    asm volatile("ldmatrix.sync.aligned.m8n8.x4.shared.b16 {%0,%1,%2,%3}, [%4];" \
                 : "=r"(r0), "=r"(r1), "=r"(r2), "=r"(r3) : "r"(a))

#define MMA16816(c, a, b) \
    asm volatile("mma.sync.aligned.m16n8k16.row.col.f32.bf16.bf16.f32 " \
                 "{%0,%1,%2,%3}, {%4,%5,%6,%7}, {%8,%9}, {%0,%1,%2,%3};" \
                 : "+f"((c)[0]), "+f"((c)[1]), "+f"((c)[2]), "+f"((c)[3]) \
                 : "r"((a)[0]), "r"((a)[1]), "r"((a)[2]), "r"((a)[3]), \
                   "r"((b)[0]), "r"((b)[1]))

// Truncation-based hi/lo split of 2 floats.
__device__ __forceinline__ void split2(float a, float b, unsigned& hp, unsigned& lp) {
    unsigned ua = __float_as_uint(a);
    unsigned ub = __float_as_uint(b);
    hp = __byte_perm(ua, ub, 0x7632);
    float la = a - __uint_as_float(ua & 0xFFFF0000u);
    float lb = b - __uint_as_float(ub & 0xFFFF0000u);
    asm("cvt.rn.bf16x2.f32 %0, %1, %2;" : "=r"(lp) : "f"(lb), "f"(la));
}

// =====================================================================
// Kernel 0: split W into hi/lo bf16
// =====================================================================
__global__ void wsplit_kernel(const float* __restrict__ Wq, const float* __restrict__ Wk)
{
    int i = blockIdx.x * 256 + threadIdx.x;
    int side = i >> 15, j = i & 32767;
    float v = (side ? Wk : Wq)[j];
    __nv_bfloat16 h = __float2bfloat16_rn(v);
    g_wh[side][j] = h;
    g_wl[side][j] = __float2bfloat16_rn(v - __bfloat162float(h));
}

// =====================================================================
// Kernel 1: HMMA split-bf16 projection (R13 best config: 64-row tiles).
// grid = (256, 2), block = 256 (8 warps: 4 M x 2 N), 3 CTAs/SM.
// =====================================================================
#define PJ_XL   8192
#define PJ_W    16384
#define PJ_SMEM 49152

__global__ __launch_bounds__(256, 3) void proj_kernel(
    const float* __restrict__ X0, const float* __restrict__ Y0,
    const float* __restrict__ bq, const float* __restrict__ bk)
{
    extern __shared__ char smem[];
    const unsigned sb = smem_u32(smem);

    const int side = blockIdx.y;
    const float* X    = side ? Y0 : X0;
    const float* bias = side ? bk : bq;
    const char* gwh = (const char*)g_wh[side];
    const char* gwl = (const char*)g_wl[side];
    float* gnorm = side ? g_kn : g_qn;
    __nv_bfloat16* gh = side ? g_kh : g_qh;
    __nv_bfloat16* gl = side ? g_kl : g_ql;
    const float scale = side ? -2.f : 1.f;

    const int r0 = blockIdx.x * 64;
    const int t  = threadIdx.x;
    const int wid = t >> 5, l = t & 31;
    const int wr = (wid & 3) * 16;
    const int wc = (wid >> 2) * 32;

    float4 xbuf[2][2];
#pragma unroll
    for (int it = 0; it < 2; ++it) {
        int c16 = t + 256 * it;
        int row = c16 >> 3, ch = c16 & 7;
        const float* src = X + (size_t)(r0 + row) * HH + ch * 8;
        xbuf[it][0] = *(const float4*)src;
        xbuf[it][1] = *(const float4*)(src + 4);
    }
#pragma unroll
    for (int it = 0; it < 4; ++it) {
        int f = t + 256 * it;
        int split = f >> 9, c = f & 511;
        int row = c >> 3, ch = c & 7;
        unsigned dst = sb + PJ_W + split * 8192 + row * 128 + ((ch * 16) ^ ((row & 7) << 4));
        CP16(dst, (split ? gwl : gwh) + row * 1024 + ch * 16);
    }
    CP_COMMIT();

    const int rowA0 = wr + (l & 7) + ((l & 8) ? 8 : 0);
    const int rowB0 = wc + (l & 7) + ((l & 16) ? 8 : 0);
    const int kbA = (l & 16) ? 16 : 0;
    const int kbB = (l & 8) ? 16 : 0;
    const int p = (l & 7) << 4;
    const unsigned aA0 = sb + rowA0 * 128;
    const unsigned aB0 = rowB0 * 128;

    float acc[4][4];
#pragma unroll
    for (int t8 = 0; t8 < 4; ++t8)
#pragma unroll
        for (int e = 0; e < 4; ++e) acc[t8][e] = 0.f;

    for (int i = 0; i < 8; ++i) {
        __syncthreads();
#pragma unroll
        for (int it = 0; it < 2; ++it) {
            int c16 = t + 256 * it;
            int row = c16 >> 3, ch = c16 & 7;
            unsigned off = row * 128 + ((ch * 16) ^ ((row & 7) << 4));
            float4 a = xbuf[it][0], b4 = xbuf[it][1];
            unsigned h0, h1, h2, h3, l0, l1, l2, l3;
            split2(a.x,  a.y,  h0, l0);
            split2(a.z,  a.w,  h1, l1);
            split2(b4.x, b4.y, h2, l2);
            split2(b4.z, b4.w, h3, l3);
            *(uint4*)(smem + off)         = make_uint4(h0, h1, h2, h3);
            *(uint4*)(smem + PJ_XL + off) = make_uint4(l0, l1, l2, l3);
        }
        if (i < 7) {
#pragma unroll
            for (int it = 0; it < 2; ++it) {
                int c16 = t + 256 * it;
                int row = c16 >> 3, ch = c16 & 7;
                const float* src = X + (size_t)(r0 + row) * HH + (i + 1) * 64 + ch * 8;
                xbuf[it][0] = *(const float4*)src;
                xbuf[it][1] = *(const float4*)(src + 4);
            }
#pragma unroll
            for (int it = 0; it < 4; ++it) {
                int f = t + 256 * it;
                int split = f >> 9, c = f & 511;
                int row = c >> 3, ch = c & 7;
                unsigned dst = sb + PJ_W + ((i + 1) & 1) * 16384 + split * 8192
                               + row * 128 + ((ch * 16) ^ ((row & 7) << 4));
                CP16(dst, (split ? gwl : gwh) + row * 1024 + (i + 1) * 128 + ch * 16);
            }
            CP_COMMIT();
            CP_WAIT1();
        } else {
            CP_WAIT0();
        }
        __syncthreads();

        const unsigned wb = sb + PJ_W + (i & 1) * 16384;
#pragma unroll
        for (int ks = 0; ks < 4; ++ks) {
            const unsigned xbA = (unsigned)((ks * 32 + kbA) ^ p);
            const unsigned xbB = (unsigned)((ks * 32 + kbB) ^ p);
            unsigned ah[4], al[4], bh[4][2], bl[4][2];
            LDSM4(ah[0], ah[1], ah[2], ah[3], aA0 + xbA);
            LDSM4(al[0], al[1], al[2], al[3], aA0 + PJ_XL + xbA);
#pragma unroll
            for (int g = 0; g < 2; ++g) {
                unsigned base = wb + aB0 + g * 2048 + xbB;
                LDSM4(bh[2 * g][0], bh[2 * g][1], bh[2 * g + 1][0], bh[2 * g + 1][1], base);
                LDSM4(bl[2 * g][0], bl[2 * g][1], bl[2 * g + 1][0], bl[2 * g + 1][1], base + 8192);
            }
#pragma unroll
            for (int t8 = 0; t8 < 4; ++t8) {
                MMA16816(acc[t8], ah, bh[t8]);
                MMA16816(acc[t8], ah, bl[t8]);
                MMA16816(acc[t8], al, bh[t8]);
            }
        }
    }

    __syncthreads();
    float* s_o = (float*)smem;
#pragma unroll
    for (int t8 = 0; t8 < 4; ++t8) {
        int col = wc + t8 * 8 + 2 * (l & 3);
        float2 b2 = *(const float2*)&bias[col];
        int row0 = wr + (l >> 2);
        s_o[row0 * 68 + col]           = acc[t8][0] + b2.x;
        s_o[row0 * 68 + col + 1]       = acc[t8][1] + b2.y;
        s_o[(row0 + 8) * 68 + col]     = acc[t8][2] + b2.x;
        s_o[(row0 + 8) * 68 + col + 1] = acc[t8][3] + b2.y;
    }
    __syncthreads();

#pragma unroll
    for (int it = 0; it < 4; ++it) {
        int f = t + 256 * it;
        int quad = f & 15, r = f >> 4;
        float4 v = *(const float4*)&s_o[r * 68 + quad * 4];
        v.x *= scale; v.y *= scale; v.z *= scale; v.w *= scale;
        unsigned hp0, hp1, lp0, lp1;
        split2(v.x, v.y, hp0, lp0);
        split2(v.z, v.w, hp1, lp1);
        size_t base = (size_t)(r0 + r) * KD + quad * 4;
        *(unsigned*)&gh[base]     = hp0;
        *(unsigned*)&gh[base + 2] = hp1;
        *(unsigned*)&gl[base]     = lp0;
        *(unsigned*)&gl[base + 2] = lp1;
    }
    if (t < 64) {
        float s = 0.f;
#pragma unroll
        for (int j = 0; j < 64; ++j) {
            float v = s_o[t * 68 + j];
            s += v * v;
        }
        gnorm[r0 + t] = s;
    }
}

// =====================================================================
// Kernel 2 (v9): hi-only HMMA argmin sweep + pipelined fused refinement.
// grid = (16, 8), block = 256 (8 warps: 4 row x 2 col groups), 2 CTAs/SM.
// =====================================================================
#define D_B     16384
#define BUFSZ   16896
#define D_RV    (D_B + 2 * BUFSZ)       /* 50176 */
#define D_RI    (D_RV + 4096)           /* 54272 */
#define D_CD    (D_RI + 4096)           /* 58368: int2 cand[128] */
#define DIST_SMEM (D_CD + 1024)         /* 59392 */
#define NT 16

__global__ __launch_bounds__(256, 2) void dist_kernel()
{
    extern __shared__ char smem[];
    const unsigned sb = smem_u32(smem);

    const int b  = blockIdx.y;
    const int n0 = blockIdx.x * 128;
    const int t  = threadIdx.x;
    const int wid = t >> 5, l = t & 31;
    const int wr = (wid & 3) * 32;
    const int wc = (wid >> 2) * 64;

    const char* gqh = (const char*)g_qh + ((size_t)b * NN + n0) * KD * 2;
    const char* gkh = (const char*)g_kh + (size_t)b * MM * KD * 2;
    const char* gkn = (const char*)g_kn + (size_t)b * MM * 4;

#pragma unroll
    for (int it = 0; it < 4; ++it) {
        int c = t + 256 * it;
        int row = c >> 3, ch = c & 7;
        unsigned dst = sb + row * 128 + ((ch * 16) ^ ((row & 7) << 4));
        CP16(dst, gqh + c * 16);
    }
#pragma unroll
    for (int it = 0; it < 4; ++it) {
        int c = t + 256 * it;
        int row = c >> 3, ch = c & 7;
        unsigned dst = sb + D_B + row * 128 + ((ch * 16) ^ ((row & 7) << 4));
        CP16(dst, gkh + c * 16);
    }
    if (t < 32) CP16(sb + D_B + 16384 + t * 16, gkn + t * 16);
    CP_COMMIT();

    {
        const char* skh = gkh + (size_t)128 * KD * 2;
        unsigned bufb = sb + D_B + BUFSZ;
#pragma unroll
        for (int it = 0; it < 4; ++it) {
            int c = t + 256 * it;
            int row = c >> 3, ch = c & 7;
            unsigned dst = bufb + row * 128 + ((ch * 16) ^ ((row & 7) << 4));
            CP16(dst, skh + c * 16);
        }
        if (t < 32) CP16(bufb + 16384 + t * 16, gkn + 512 + t * 16);
        CP_COMMIT();
    }

    const int rowA0 = wr + (l & 7) + ((l & 8) ? 8 : 0);
    const int rowB0 = wc + (l & 7) + ((l & 16) ? 8 : 0);
    const int kbA = (l & 16) ? 16 : 0;
    const int kbB = (l & 8) ? 16 : 0;
    const int p = (l & 7) << 4;
    const unsigned aA0 = sb + rowA0 * 128;
    const unsigned aB0 = rowB0 * 128;

    CP_WAIT1();
    __syncthreads();

    float minv[4];
    int   mini[4];
#pragma unroll
    for (int s = 0; s < 4; ++s) { minv[s] = 1e30f; mini[s] = 0; }

    for (int i = 0; i < NT; ++i) {
        const unsigned bufb = sb + D_B + (i & 1) * BUFSZ;

        float acc[2][8][4];
#pragma unroll
        for (int t8 = 0; t8 < 8; ++t8) {
            float2 kn2 = *(const float2*)(smem + D_B + (i & 1) * BUFSZ + 16384
                                          + (wc + t8 * 8 + 2 * (l & 3)) * 4);
#pragma unroll
            for (int f = 0; f < 2; ++f) {
                acc[f][t8][0] = kn2.x; acc[f][t8][1] = kn2.y;
                acc[f][t8][2] = kn2.x; acc[f][t8][3] = kn2.y;
            }
        }

#pragma unroll
        for (int ks = 0; ks < 4; ++ks) {
            const unsigned xbA = (unsigned)((ks * 32 + kbA) ^ p);
            const unsigned xbB = (unsigned)((ks * 32 + kbB) ^ p);
            unsigned ah[2][4], bh[8][2];
#pragma unroll
            for (int f = 0; f < 2; ++f)
                LDSM4(ah[f][0], ah[f][1], ah[f][2], ah[f][3], aA0 + f * 2048 + xbA);
#pragma unroll
            for (int g = 0; g < 4; ++g) {
                unsigned base = bufb + aB0 + g * 2048 + xbB;
                LDSM4(bh[2 * g][0], bh[2 * g][1], bh[2 * g + 1][0], bh[2 * g + 1][1], base);
            }
#pragma unroll
            for (int f = 0; f < 2; ++f)
#pragma unroll
                for (int t8 = 0; t8 < 8; ++t8)
                    MMA16816(acc[f][t8], ah[f], bh[t8]);
        }

        const int mbase = i * 128 + wc + 2 * (l & 3);
#pragma unroll
        for (int f = 0; f < 2; ++f)
#pragma unroll
            for (int t8 = 0; t8 < 8; ++t8) {
                int m0 = mbase + t8 * 8;
                float v0 = acc[f][t8][0], v1 = acc[f][t8][1];
                float v2 = acc[f][t8][2], v3 = acc[f][t8][3];
                int s0 = f * 2, s1 = f * 2 + 1;
                float m01 = fminf(v0, v1);
                int   i01 = (v1 < v0) ? m0 + 1 : m0;
                mini[s0] = (m01 < minv[s0]) ? i01 : mini[s0];
                minv[s0] = fminf(m01, minv[s0]);
                float m23 = fminf(v2, v3);
                int   i23 = (v3 < v2) ? m0 + 1 : m0;
                mini[s1] = (m23 < minv[s1]) ? i23 : mini[s1];
                minv[s1] = fminf(m23, minv[s1]);
            }

        __syncthreads();
        if (i + 2 < NT) {
            const char* skh = gkh + (size_t)(i + 2) * 128 * KD * 2;
            unsigned nbuf = sb + D_B + (i & 1) * BUFSZ;
#pragma unroll
            for (int it = 0; it < 4; ++it) {
                int c = t + 256 * it;
                int row = c >> 3, ch = c & 7;
                unsigned dst = nbuf + row * 128 + ((ch * 16) ^ ((row & 7) << 4));
                CP16(dst, skh + c * 16);
            }
            if (t < 32) CP16(nbuf + 16384 + t * 16, gkn + (size_t)(i + 2) * 512 + t * 16);
            CP_COMMIT();
            CP_WAIT1();
            __syncthreads();
        } else if (i + 1 < NT) {
            CP_WAIT0();
            __syncthreads();
        }
    }

    float* s_rv = (float*)(smem + D_RV);
    int*   s_ri = (int*)(smem + D_RI);
    int2*  s_cd = (int2*)(smem + D_CD);
#pragma unroll
    for (int f = 0; f < 2; ++f)
#pragma unroll
        for (int h = 0; h < 2; ++h) {
            int row = wr + f * 16 + (l >> 2) + h * 8;
            int col8 = (wid >> 2) * 4 + (l & 3);
            s_rv[row * 8 + col8] = minv[f * 2 + h];
            s_ri[row * 8 + col8] = mini[f * 2 + h];
        }
    __syncthreads();
    if (t < 128) {
        float bv1 = 1e30f, bv2 = 1e30f;
        int bi1 = 0, bi2 = 0;
#pragma unroll
        for (int j = 0; j < 8; ++j) {
            float v = s_rv[t * 8 + j];
            int   m = s_ri[t * 8 + j];
            bool better1 = v < bv1;
            float ov = bv1; int oi = bi1;
            bv1 = better1 ? v : bv1;  bi1 = better1 ? m : bi1;
            float cv = better1 ? ov : v;
            int   ci = better1 ? oi : m;
            bool better2 = cv < bv2;
            bv2 = better2 ? cv : bv2; bi2 = better2 ? ci : bi2;
        }
        s_cd[t] = make_int2(bi1, bi2);
    }
    __syncthreads();

    // ---- pipelined fused exact refinement: 4 rows per batch for MLP.
    // half-warp per candidate; lane ll covers 4 dims per u-step.
    {
        const unsigned* uqh = (const unsigned*)g_qh;
        const unsigned* uql = (const unsigned*)g_ql;
        const unsigned* ukh = (const unsigned*)g_kh;
        const unsigned* ukl = (const unsigned*)g_kl;
        const int ll = l & 15;
#pragma unroll
        for (int r4 = 0; r4 < 4; ++r4) {
            float dots[4];
            // load + fma phase: 4 independent rows' chains -> deep MLP
#pragma unroll
            for (int rr = 0; rr < 4; ++rr) {
                int row = wid * 16 + r4 * 4 + rr;
                int grow = b * NN + n0 + row;
                int2 cd = s_cd[row];
                int c = (l < 16) ? cd.x : cd.y;
                size_t qb = (size_t)grow * 32 + ll * 2;
                size_t kb = ((size_t)b * MM + c) * 32 + ll * 2;
                float dot = (ll == 0) ? g_kn[b * MM + c] : 0.f;
#pragma unroll
                for (int u = 0; u < 2; ++u) {
                    float2 qh = __bfloat1622float2(*(const __nv_bfloat162*)&uqh[qb + u]);
                    float2 ql = __bfloat1622float2(*(const __nv_bfloat162*)&uql[qb + u]);
                    float2 kh = __bfloat1622float2(*(const __nv_bfloat162*)&ukh[kb + u]);
                    float2 kl = __bfloat1622float2(*(const __nv_bfloat162*)&ukl[kb + u]);
                    float q0 = qh.x + ql.x, q1 = qh.y + ql.y;
                    float k0 = kh.x + kl.x, k1 = kh.y + kl.y;
                    dot = fmaf(q0, k0, dot);
                    dot = fmaf(q1, k1, dot);
                }
                dots[rr] = dot;
            }
            // reduce + write phase
#pragma unroll
            for (int rr = 0; rr < 4; ++rr) {
                int row = wid * 16 + r4 * 4 + rr;
                int grow = b * NN + n0 + row;
                float dot = dots[rr];
#pragma unroll
                for (int off = 8; off > 0; off >>= 1)
                    dot += __shfl_xor_sync(0xFFFFFFFFu, dot, off);
                float other = __shfl_xor_sync(0xFFFFFFFFu, dot, 16);
                if (l == 0) {
                    float dmin = fminf(dot, other) + g_qn[grow];
                    g_w[grow] = expf(-dmin);
                }
            }
        }
    }
}

// =====================================================================
// Kernel 3: rank-1 outer product, 4 rows per CTA, streaming stores.
// =====================================================================
__global__ __launch_bounds__(256) void outer_kernel(float* __restrict__ out)
{
    const int b = blockIdx.y;
    const int n0 = blockIdx.x * 4;
    const float* wrow = &g_w[b * NN];
    const float w0 = wrow[n0], w1 = wrow[n0 + 1], w2 = wrow[n0 + 2], w3 = wrow[n0 + 3];
    const float4* wv = (const float4*)wrow;
    float4* o = (float4*)(out + ((size_t)b * NN + n0) * MM);
#pragma unroll
    for (int it = 0; it < 2; ++it) {
        int j = threadIdx.x + 256 * it;
        float4 v = wv[j];
        __stcs(&o[j],        make_float4(w0 * v.x, w0 * v.y, w0 * v.z, w0 * v.w));
        __stcs(&o[j + 512],  make_float4(w1 * v.x, w1 * v.y, w1 * v.z, w1 * v.w));
        __stcs(&o[j + 1024], make_float4(w2 * v.x, w2 * v.y, w2 * v.z, w2 * v.w));
        __stcs(&o[j + 1536], make_float4(w3 * v.x, w3 * v.y, w3 * v.z, w3 * v.w));
    }
}

// =====================================================================
extern "C" void kernel_launch(void* const* d_in, const int* in_sizes, int n_in,
                              void* d_out, int out_size)
{
    const float* x  = (const float*)d_in[0];
    const float* y  = (const float*)d_in[1];
    const float* Wq = (const float*)d_in[2];
    const float* bq = (const float*)d_in[3];
    const float* Wk = (const float*)d_in[4];
    const float* bk = (const float*)d_in[5];
    float* out = (float*)d_out;

    cudaFuncSetAttribute(proj_kernel, cudaFuncAttributeMaxDynamicSharedMemorySize, PJ_SMEM);
    cudaFuncSetAttribute(dist_kernel, cudaFuncAttributeMaxDynamicSharedMemorySize, DIST_SMEM);

    wsplit_kernel<<<256, 256>>>(Wq, Wk);
    proj_kernel<<<dim3(NN * BB / 64, 2), 256, PJ_SMEM>>>(x, y, bq, bk);
    dist_kernel<<<dim3(NN / 128, BB), 256, DIST_SMEM>>>();
    outer_kernel<<<dim3(NN / 4, BB), 256>>>(out);
}